// round 5
// baseline (speedup 1.0000x reference)
#include <cuda_runtime.h>

#define NN 131072
#define DD 128
#define EE 2097152
#define BBG 16
#define EPSV 1e-5f

#define SA_S 68    // padded stride for conv sA chunks
#define FA_S 132   // padded stride for fused full-K sA

// ---------------- device scratch (no allocations allowed) ----------------
__device__ float g_A[NN * DD];
__device__ float g_B[NN * DD];
__device__ float g_C[NN * DD];
__device__ float g_a1[NN * DD];
__device__ float g_a2[NN * DD];
__device__ float g_a3[NN * DD];
__device__ float g_convw[3 * 3 * DD * DD];
__device__ float g_stats[12 * DD];
__device__ float g_hg[BBG * 3 * DD];
// CSR scratch
__device__ uint2 g_meta[EE];
__device__ int g_deg[NN];
__device__ int g_off[NN + 1];
__device__ int g_cur[NN];
__device__ int g_part[128];

// ---------------- small kernels ----------------
__global__ void prep_conv_w(const float* __restrict__ w1,
                            const float* __restrict__ w2,
                            const float* __restrict__ w3) {
    int idx = blockIdx.x * blockDim.x + threadIdx.x;
    if (idx >= 3 * DD * DD) return;
    int o = idx % DD;
    int i = (idx / DD) % DD;
    int t = idx / (DD * DD);
    g_convw[((0 * 3 + t) * DD + i) * DD + o] = w1[(o * DD + i) * 3 + t];
    g_convw[((1 * 3 + t) * DD + i) * DD + o] = w2[(o * DD + i) * 3 + t];
    g_convw[((2 * 3 + t) * DD + i) * DD + o] = w3[(o * DD + i) * 3 + t];
}

__global__ void zero_stats_hg() {
    int i = blockIdx.x * blockDim.x + threadIdx.x;
    if (i < 12 * DD) g_stats[i] = 0.f;
    if (i < BBG * 3 * DD) g_hg[i] = 0.f;
}

// ---------------- CSR build ----------------
__global__ void zero_degcur() {
    int i = blockIdx.x * blockDim.x + threadIdx.x;
    if (i < NN) { g_deg[i] = 0; g_cur[i] = 0; }
}

__global__ void hist_dst(const int* __restrict__ dst) {
    int e = blockIdx.x * blockDim.x + threadIdx.x;
    if (e < EE) atomicAdd(&g_deg[dst[e]], 1);
}

__global__ void scan1() {
    __shared__ int sm[1024];
    int t = threadIdx.x;
    int i = blockIdx.x * 1024 + t;
    int v = g_deg[i];
    sm[t] = v;
    __syncthreads();
    for (int d = 1; d < 1024; d <<= 1) {
        int tmp = (t >= d) ? sm[t - d] : 0;
        __syncthreads();
        sm[t] += tmp;
        __syncthreads();
    }
    g_off[i] = sm[t] - v;
    if (t == 1023) g_part[blockIdx.x] = sm[1023];
}

__global__ void scan2() {
    __shared__ int sm[128];
    int t = threadIdx.x;
    int v = g_part[t];
    sm[t] = v;
    __syncthreads();
    for (int d = 1; d < 128; d <<= 1) {
        int tmp = (t >= d) ? sm[t - d] : 0;
        __syncthreads();
        sm[t] += tmp;
        __syncthreads();
    }
    g_part[t] = sm[t] - v;
    if (t == 0) g_off[NN] = EE;
}

__global__ void scan3() {
    int i = blockIdx.x * 1024 + threadIdx.x;
    g_off[i] += g_part[blockIdx.x];
}

__global__ void csr_fill(const int* __restrict__ src, const int* __restrict__ dst,
                         const float* __restrict__ ew) {
    int e = blockIdx.x * blockDim.x + threadIdx.x;
    if (e >= EE) return;
    int d = dst[e];
    int pos = g_off[d] + atomicAdd(&g_cur[d], 1);
    g_meta[pos] = make_uint2((unsigned)src[e], __float_as_uint(ew[e]));
}

// ---------------- packed f32x2 GEMM helpers ----------------
__device__ __forceinline__ void load_sB(float* __restrict__ sB,
                                        const float* __restrict__ W,
                                        int k0, int tid) {
#pragma unroll
    for (int p = 0; p < 8; p++) {
        int idx = p * 256 + tid;
        int kr = idx >> 5, c4 = idx & 31;
        ((float4*)(sB + kr * 128))[c4] = ((const float4*)(W + (k0 + kr) * DD))[c4];
    }
}

__device__ __forceinline__ void epilogue(unsigned long long acc[8][4],
                                         const float* __restrict__ bias,
                                         float* __restrict__ out,
                                         int base, int r0, int c0, int relu) {
    float4 bv0 = *(const float4*)(bias + c0);
    float4 bv1 = *(const float4*)(bias + c0 + 4);
    float bb[8] = {bv0.x, bv0.y, bv0.z, bv0.w, bv1.x, bv1.y, bv1.z, bv1.w};
#pragma unroll
    for (int i = 0; i < 8; i++) {
        float v[8];
#pragma unroll
        for (int j = 0; j < 4; j++) {
            float lo, hi;
            asm("mov.b64 {%0, %1}, %2;" : "=f"(lo), "=f"(hi) : "l"(acc[i][j]));
            v[2 * j] = lo; v[2 * j + 1] = hi;
        }
        float4 o0, o1;
        if (relu) {
            o0.x = fmaxf(v[0] + bb[0], 0.f); o0.y = fmaxf(v[1] + bb[1], 0.f);
            o0.z = fmaxf(v[2] + bb[2], 0.f); o0.w = fmaxf(v[3] + bb[3], 0.f);
            o1.x = fmaxf(v[4] + bb[4], 0.f); o1.y = fmaxf(v[5] + bb[5], 0.f);
            o1.z = fmaxf(v[6] + bb[6], 0.f); o1.w = fmaxf(v[7] + bb[7], 0.f);
        } else {
            o0.x = v[0] + bb[0]; o0.y = v[1] + bb[1];
            o0.z = v[2] + bb[2]; o0.w = v[3] + bb[3];
            o1.x = v[4] + bb[4]; o1.y = v[5] + bb[5];
            o1.z = v[6] + bb[6]; o1.w = v[7] + bb[7];
        }
        float* po = out + (base + r0 + i) * DD + c0;
        ((float4*)po)[0] = o0;
        ((float4*)(po + 4))[0] = o1;
    }
}

// ---------------- fused graph conv: gather -> smem -> GEMM + bias + relu ----------
__global__ __launch_bounds__(256, 2) void gconv_fused(
    const float* __restrict__ H, const float* __restrict__ W,
    const float* __restrict__ bias, float* __restrict__ out) {
    extern __shared__ float sm[];
    float* sA = sm;                  // [128][FA_S]
    float* sB = sm + 128 * FA_S;     // [64][128]
    const int tid = threadIdx.x;
    const int warp = tid >> 5, lane = tid & 31;
    const int base = blockIdx.x * 128;

    // ---- gather phase: each warp aggregates 16 nodes into sA rows ----
    for (int i = 0; i < 16; i++) {
        int row = warp * 16 + i;
        int node = base + row;
        int beg = g_off[node], end = g_off[node + 1];
        float4 acc = make_float4(0.f, 0.f, 0.f, 0.f);
        for (int b = beg; b < end; b += 32) {
            int n = min(32, end - b);
            uint2 m = (b + lane < end) ? g_meta[b + lane] : make_uint2(0u, 0u);
#pragma unroll 4
            for (int j = 0; j < n; j++) {
                int s = __shfl_sync(0xffffffffu, (int)m.x, j);
                float w = __int_as_float(__shfl_sync(0xffffffffu, (int)m.y, j));
                float4 v = __ldg(((const float4*)H) + s * 32 + lane);
                acc.x = fmaf(v.x, w, acc.x);
                acc.y = fmaf(v.y, w, acc.y);
                acc.z = fmaf(v.z, w, acc.z);
                acc.w = fmaf(v.w, w, acc.w);
            }
        }
        *(float4*)(sA + row * FA_S + lane * 4) = acc;
    }

    // ---- GEMM phase ----
    const int ty = tid >> 4, tx = tid & 15;
    const int r0 = ty * 8, c0 = tx * 8;
    unsigned long long acc[8][4];
#pragma unroll
    for (int i = 0; i < 8; i++)
#pragma unroll
        for (int j = 0; j < 4; j++) acc[i][j] = 0ull;

#pragma unroll
    for (int kc = 0; kc < 2; kc++) {
        __syncthreads();
        load_sB(sB, W, kc * 64, tid);
        __syncthreads();
        const int kb = kc * 64;
#pragma unroll 8
        for (int k = 0; k < 64; k++) {
            ulonglong2 b01 = *(const ulonglong2*)(sB + k * 128 + c0);
            ulonglong2 b23 = *(const ulonglong2*)(sB + k * 128 + c0 + 4);
            unsigned long long bp0 = b01.x, bp1 = b01.y, bp2 = b23.x, bp3 = b23.y;
#pragma unroll
            for (int i = 0; i < 8; i++) {
                float a = sA[(r0 + i) * FA_S + kb + k];
                unsigned long long aa;
                asm("mov.b64 %0, {%1, %1};" : "=l"(aa) : "f"(a));
                asm("fma.rn.f32x2 %0, %1, %2, %0;" : "+l"(acc[i][0]) : "l"(aa), "l"(bp0));
                asm("fma.rn.f32x2 %0, %1, %2, %0;" : "+l"(acc[i][1]) : "l"(aa), "l"(bp1));
                asm("fma.rn.f32x2 %0, %1, %2, %0;" : "+l"(acc[i][2]) : "l"(aa), "l"(bp2));
                asm("fma.rn.f32x2 %0, %1, %2, %0;" : "+l"(acc[i][3]) : "l"(aa), "l"(bp3));
            }
        }
    }
    epilogue(acc, bias, out, base, r0, c0, 1);
}

// ---------------- conv (dense front-end), unchanged from R3 ----------------
__device__ __forceinline__ void load_sA_g(float* __restrict__ sA,
                                          const float* __restrict__ A,
                                          int base_row, int k0, int tid) {
#pragma unroll
    for (int p = 0; p < 8; p++) {
        int idx = p * 256 + tid;
        int row = idx >> 4, kq = idx & 15;
        int gr = base_row + row;
        float4 v = make_float4(0.f, 0.f, 0.f, 0.f);
        if (gr >= 0 && gr < NN) v = ((const float4*)(A + gr * DD + k0))[kq];
        *(float4*)(sA + row * SA_S + kq * 4) = v;
    }
}

__global__ __launch_bounds__(256, 2) void conv128_f2(
    const float* __restrict__ X, const float* __restrict__ W3,
    const float* __restrict__ bias, float* __restrict__ out, int dil) {
    extern __shared__ float sm[];
    float* sA = sm;
    float* sB = sm + 128 * SA_S;
    const int tid = threadIdx.x;
    const int base = blockIdx.x * 128;
    const int ty = tid >> 4, tx = tid & 15;
    const int r0 = ty * 8, c0 = tx * 8;

    unsigned long long acc[8][4];
#pragma unroll
    for (int i = 0; i < 8; i++)
#pragma unroll
        for (int j = 0; j < 4; j++) acc[i][j] = 0ull;

    for (int tp = 0; tp < 3; tp++) {
        const int shift = (tp - 1) * dil;
        const float* Wt = W3 + tp * DD * DD;
#pragma unroll
        for (int kc = 0; kc < 2; kc++) {
            load_sA_g(sA, X, base + shift, kc * 64, tid);
            load_sB(sB, Wt, kc * 64, tid);
            __syncthreads();
#pragma unroll 8
            for (int k = 0; k < 64; k++) {
                ulonglong2 b01 = *(const ulonglong2*)(sB + k * 128 + c0);
                ulonglong2 b23 = *(const ulonglong2*)(sB + k * 128 + c0 + 4);
                unsigned long long bp0 = b01.x, bp1 = b01.y, bp2 = b23.x, bp3 = b23.y;
#pragma unroll
                for (int i = 0; i < 8; i++) {
                    float a = sA[(r0 + i) * SA_S + k];
                    unsigned long long aa;
                    asm("mov.b64 %0, {%1, %1};" : "=l"(aa) : "f"(a));
                    asm("fma.rn.f32x2 %0, %1, %2, %0;" : "+l"(acc[i][0]) : "l"(aa), "l"(bp0));
                    asm("fma.rn.f32x2 %0, %1, %2, %0;" : "+l"(acc[i][1]) : "l"(aa), "l"(bp1));
                    asm("fma.rn.f32x2 %0, %1, %2, %0;" : "+l"(acc[i][2]) : "l"(aa), "l"(bp2));
                    asm("fma.rn.f32x2 %0, %1, %2, %0;" : "+l"(acc[i][3]) : "l"(aa), "l"(bp3));
                }
            }
            __syncthreads();
        }
    }
    epilogue(acc, bias, out, base, r0, c0, 0);
}

// ---------------- BN stats / apply ----------------
__global__ void bn3_stats(const float* __restrict__ c1, const float* __restrict__ c2,
                          const float* __restrict__ c3) {
    const int ch = threadIdx.x;
    const int rows = NN / 512;
    const int r0 = blockIdx.x * rows;
    float s1 = 0, q1 = 0, s2 = 0, q2 = 0, s3 = 0, q3 = 0;
    for (int r = r0; r < r0 + rows; r++) {
        int o = r * DD + ch;
        float v1 = c1[o], v2 = c2[o], v3 = c3[o];
        float x1 = fmaxf(v1, 0.f) + v2;
        float x2 = fmaxf(v2, 0.f) + v3;
        float x3 = fmaxf(v3, 0.f) + v1;
        s1 += x1; q1 = fmaf(x1, x1, q1);
        s2 += x2; q2 = fmaf(x2, x2, q2);
        s3 += x3; q3 = fmaf(x3, x3, q3);
    }
    atomicAdd(&g_stats[0 * DD + ch], s1); atomicAdd(&g_stats[1 * DD + ch], q1);
    atomicAdd(&g_stats[2 * DD + ch], s2); atomicAdd(&g_stats[3 * DD + ch], q2);
    atomicAdd(&g_stats[4 * DD + ch], s3); atomicAdd(&g_stats[5 * DD + ch], q3);
}

__global__ void bn3_apply(float* __restrict__ c1, float* __restrict__ c2,
                          float* __restrict__ c3, const float* __restrict__ g,
                          const float* __restrict__ b) {
    int idx = blockIdx.x * blockDim.x + threadIdx.x;
    int ch = idx & (DD - 1);
    float v1 = c1[idx], v2 = c2[idx], v3 = c3[idx];
    float x1 = fmaxf(v1, 0.f) + v2;
    float x2 = fmaxf(v2, 0.f) + v3;
    float x3 = fmaxf(v3, 0.f) + v1;
    const float inv = 1.f / (float)NN;
    float mu1 = g_stats[0 * DD + ch] * inv;
    float va1 = g_stats[1 * DD + ch] * inv - mu1 * mu1;
    float mu2 = g_stats[2 * DD + ch] * inv;
    float va2 = g_stats[3 * DD + ch] * inv - mu2 * mu2;
    float mu3 = g_stats[4 * DD + ch] * inv;
    float va3 = g_stats[5 * DD + ch] * inv - mu3 * mu3;
    float gg = g[ch], bb = b[ch];
    c1[idx] = (x1 - mu1) * rsqrtf(va1 + EPSV) * gg + bb;
    c2[idx] = (x2 - mu2) * rsqrtf(va2 + EPSV) * gg + bb;
    c3[idx] = (x3 - mu3) * rsqrtf(va3 + EPSV) * gg + bb;
}

__global__ void bn1_apply(float* __restrict__ x, const float* __restrict__ g,
                          const float* __restrict__ b) {
    int idx = blockIdx.x * blockDim.x + threadIdx.x;
    int ch = idx & (DD - 1);
    const float inv = 1.f / (float)NN;
    float mu = g_stats[ch] * inv;
    float va = g_stats[DD + ch] * inv - mu * mu;
    x[idx] = (x[idx] - mu) * rsqrtf(va + EPSV) * g[ch] + b[ch];
}

// ---------------- press conv fused with bn1 stats ----------------
__global__ void press_stats(const float* __restrict__ a1, const float* __restrict__ a2,
                            const float* __restrict__ a3, const float* __restrict__ pw,
                            const float* __restrict__ pb, float* __restrict__ out) {
    const int d = threadIdx.x;
    const int rows = NN / 512;
    const int r0 = blockIdx.x * rows;
    float w00 = pw[0], w01 = pw[1], w02 = pw[2];
    float w10 = pw[3], w11 = pw[4], w12 = pw[5];
    float w20 = pw[6], w21 = pw[7], w22 = pw[8];
    float pbias = pb[0];
    float s = 0.f, q = 0.f;
    for (int r = r0; r < r0 + rows; r++) {
        const float* p1 = a1 + r * DD;
        const float* p2 = a2 + r * DD;
        const float* p3 = a3 + r * DD;
        float acc = pbias;
        if (d > 0) acc += w00 * p1[d - 1] + w10 * p2[d - 1] + w20 * p3[d - 1];
        acc += w01 * p1[d] + w11 * p2[d] + w21 * p3[d];
        if (d < 127) acc += w02 * p1[d + 1] + w12 * p2[d + 1] + w22 * p3[d + 1];
        out[r * DD + d] = acc;
        s += acc; q = fmaf(acc, acc, q);
    }
    atomicAdd(&g_stats[d], s);
    atomicAdd(&g_stats[DD + d], q);
}

// ---------------- per-graph pooling (node_gid sorted) ----------------
__global__ void pool_kernel(const float* __restrict__ h2, const float* __restrict__ h3,
                            const float* __restrict__ h4, const int* __restrict__ gid) {
    const int ch = threadIdx.x;
    const int rows = NN / 512;
    const int r0 = blockIdx.x * rows;
    int cur = gid[r0];
    float s2 = 0, s3 = 0, s4 = 0;
    for (int r = r0; r < r0 + rows; r++) {
        int g = gid[r];
        if (g != cur) {
            atomicAdd(&g_hg[cur * 3 * DD + ch], s2);
            atomicAdd(&g_hg[cur * 3 * DD + DD + ch], s3);
            atomicAdd(&g_hg[cur * 3 * DD + 2 * DD + ch], s4);
            s2 = s3 = s4 = 0;
            cur = g;
        }
        int o = r * DD + ch;
        s2 += h2[o]; s3 += h3[o]; s4 += h4[o];
    }
    atomicAdd(&g_hg[cur * 3 * DD + ch], s2);
    atomicAdd(&g_hg[cur * 3 * DD + DD + ch], s3);
    atomicAdd(&g_hg[cur * 3 * DD + 2 * DD + ch], s4);
}

// ---------------- final classifier ----------------
__global__ void classify(const float* __restrict__ cl1w, const float* __restrict__ cl1b,
                         const float* __restrict__ cl2w, const float* __restrict__ cl2b,
                         float* __restrict__ out) {
    __shared__ float mid[DD];
    int t = threadIdx.x;
    for (int b = 0; b < BBG; b++) {
        float acc = cl1b[t];
        for (int k = 0; k < 3 * DD; k++) acc = fmaf(g_hg[b * 3 * DD + k], cl1w[t * 3 * DD + k], acc);
        mid[t] = acc;
        __syncthreads();
        if (t < 5) {
            float o = cl2b[t];
            for (int k = 0; k < DD; k++) o = fmaf(mid[k], cl2w[t * DD + k], o);
            out[b * 5 + t] = o;
        }
        __syncthreads();
    }
}

// ---------------- host launch ----------------
extern "C" void kernel_launch(void* const* d_in, const int* in_sizes, int n_in,
                              void* d_out, int out_size) {
    int o = (in_sizes[5] == 1) ? 6 : 5;
    const float* h   = (const float*)d_in[0];
    const float* ew  = (const float*)d_in[1];
    const int*   src = (const int*)d_in[2];
    const int*   dst = (const int*)d_in[3];
    const int*   gid = (const int*)d_in[4];
    const float* c1w = (const float*)d_in[o + 0];
    const float* c1b = (const float*)d_in[o + 1];
    const float* c2w = (const float*)d_in[o + 2];
    const float* c2b = (const float*)d_in[o + 3];
    const float* c3w = (const float*)d_in[o + 4];
    const float* c3b = (const float*)d_in[o + 5];
    const float* pw  = (const float*)d_in[o + 6];
    const float* pb  = (const float*)d_in[o + 7];
    const float* g11w = (const float*)d_in[o + 8];
    const float* g11b = (const float*)d_in[o + 9];
    const float* g12w = (const float*)d_in[o + 10];
    const float* g12b = (const float*)d_in[o + 11];
    const float* g13w = (const float*)d_in[o + 12];
    const float* g13b = (const float*)d_in[o + 13];
    const float* g2w  = (const float*)d_in[o + 14];
    const float* g2b  = (const float*)d_in[o + 15];
    const float* g3w  = (const float*)d_in[o + 16];
    const float* g3b  = (const float*)d_in[o + 17];
    const float* g4w  = (const float*)d_in[o + 18];
    const float* g4b  = (const float*)d_in[o + 19];
    const float* bng  = (const float*)d_in[o + 20];
    const float* bnb  = (const float*)d_in[o + 21];
    const float* cl1w = (const float*)d_in[o + 22];
    const float* cl1b = (const float*)d_in[o + 23];
    const float* cl2w = (const float*)d_in[o + 24];
    const float* cl2b = (const float*)d_in[o + 25];
    float* out = (float*)d_out;

    float *A, *B, *C, *a1, *a2, *a3, *convw;
    cudaGetSymbolAddress((void**)&A, g_A);
    cudaGetSymbolAddress((void**)&B, g_B);
    cudaGetSymbolAddress((void**)&C, g_C);
    cudaGetSymbolAddress((void**)&a1, g_a1);
    cudaGetSymbolAddress((void**)&a2, g_a2);
    cudaGetSymbolAddress((void**)&a3, g_a3);
    cudaGetSymbolAddress((void**)&convw, g_convw);

    const int CONV_SMEM = (128 * SA_S + 64 * 128) * 4;
    const int FUSE_SMEM = (128 * FA_S + 64 * 128) * 4;
    cudaFuncSetAttribute(conv128_f2, cudaFuncAttributeMaxDynamicSharedMemorySize, CONV_SMEM);
    cudaFuncSetAttribute(gconv_fused, cudaFuncAttributeMaxDynamicSharedMemorySize, FUSE_SMEM);

    // ---- CSR build ----
    zero_degcur<<<NN / 512, 512>>>();
    hist_dst<<<EE / 512, 512>>>(dst);
    scan1<<<128, 1024>>>();
    scan2<<<1, 128>>>();
    scan3<<<128, 1024>>>();
    csr_fill<<<EE / 512, 512>>>(src, dst, ew);

    // ---- dense front-end ----
    prep_conv_w<<<(3 * DD * DD + 255) / 256, 256>>>(c1w, c2w, c3w);
    conv128_f2<<<NN / 128, 256, CONV_SMEM>>>(h, convw + 0 * 3 * DD * DD, c1b, A, 1);
    conv128_f2<<<NN / 128, 256, CONV_SMEM>>>(h, convw + 1 * 3 * DD * DD, c2b, B, 2);
    conv128_f2<<<NN / 128, 256, CONV_SMEM>>>(h, convw + 2 * 3 * DD * DD, c3b, C, 3);

    zero_stats_hg<<<24, 256>>>();
    bn3_stats<<<512, DD>>>(A, B, C);
    bn3_apply<<<NN * DD / 256, 256>>>(A, B, C, bng, bnb);

    gconv_fused<<<NN / 128, 256, FUSE_SMEM>>>(A, g11w, g11b, a1);
    gconv_fused<<<NN / 128, 256, FUSE_SMEM>>>(B, g12w, g12b, a2);
    gconv_fused<<<NN / 128, 256, FUSE_SMEM>>>(C, g13w, g13b, a3);

    zero_stats_hg<<<24, 256>>>();
    press_stats<<<512, DD>>>(a1, a2, a3, pw, pb, A);
    bn1_apply<<<NN * DD / 256, 256>>>(A, bng, bnb);

    gconv_fused<<<NN / 128, 256, FUSE_SMEM>>>(A, g2w, g2b, B);   // ac_h2
    gconv_fused<<<NN / 128, 256, FUSE_SMEM>>>(B, g3w, g3b, C);   // ac_h3
    gconv_fused<<<NN / 128, 256, FUSE_SMEM>>>(C, g4w, g4b, a1);  // ac_h4

    pool_kernel<<<512, DD>>>(B, C, a1, gid);
    classify<<<1, DD>>>(cl1w, cl1b, cl2w, cl2b, out);
}

// round 6
// speedup vs baseline: 1.2321x; 1.2321x over previous
#include <cuda_runtime.h>

#define NN 131072
#define DD 128
#define EE 2097152
#define BBG 16
#define EPSV 1e-5f

#define SA_S 68   // padded stride for sA [row][k] chunk (64 k + pad)

// ---------------- device scratch (no allocations allowed) ----------------
__device__ float g_A[NN * DD];
__device__ float g_B[NN * DD];
__device__ float g_C[NN * DD];
__device__ float g_a1[NN * DD];
__device__ float g_a2[NN * DD];
__device__ float g_a3[NN * DD];
__device__ float g_agg[NN * DD];
__device__ float g_convw[3 * 3 * DD * DD];
__device__ float g_stats[12 * DD];
__device__ float g_hg[BBG * 3 * DD];
// CSR scratch
__device__ uint2 g_meta[EE];
__device__ int g_deg[NN];
__device__ int g_off[NN + 1];
__device__ int g_cur[NN];
__device__ int g_part[128];

// ---------------- small kernels ----------------
__global__ void prep_conv_w(const float* __restrict__ w1,
                            const float* __restrict__ w2,
                            const float* __restrict__ w3) {
    int idx = blockIdx.x * blockDim.x + threadIdx.x;
    if (idx >= 3 * DD * DD) return;
    int o = idx % DD;
    int i = (idx / DD) % DD;
    int t = idx / (DD * DD);
    g_convw[((0 * 3 + t) * DD + i) * DD + o] = w1[(o * DD + i) * 3 + t];
    g_convw[((1 * 3 + t) * DD + i) * DD + o] = w2[(o * DD + i) * 3 + t];
    g_convw[((2 * 3 + t) * DD + i) * DD + o] = w3[(o * DD + i) * 3 + t];
}

__global__ void zero_stats_hg() {
    int i = blockIdx.x * blockDim.x + threadIdx.x;
    if (i < 12 * DD) g_stats[i] = 0.f;
    if (i < BBG * 3 * DD) g_hg[i] = 0.f;
}

// ---------------- CSR build ----------------
__global__ void zero_degcur() {
    int i = blockIdx.x * blockDim.x + threadIdx.x;
    if (i < NN) { g_deg[i] = 0; g_cur[i] = 0; }
}

__global__ void hist_dst(const int* __restrict__ dst) {
    int e = blockIdx.x * blockDim.x + threadIdx.x;
    if (e < EE) atomicAdd(&g_deg[dst[e]], 1);
}

__global__ void scan1() {
    __shared__ int sm[1024];
    int t = threadIdx.x;
    int i = blockIdx.x * 1024 + t;
    int v = g_deg[i];
    sm[t] = v;
    __syncthreads();
    for (int d = 1; d < 1024; d <<= 1) {
        int tmp = (t >= d) ? sm[t - d] : 0;
        __syncthreads();
        sm[t] += tmp;
        __syncthreads();
    }
    g_off[i] = sm[t] - v;
    if (t == 1023) g_part[blockIdx.x] = sm[1023];
}

__global__ void scan2() {
    __shared__ int sm[128];
    int t = threadIdx.x;
    int v = g_part[t];
    sm[t] = v;
    __syncthreads();
    for (int d = 1; d < 128; d <<= 1) {
        int tmp = (t >= d) ? sm[t - d] : 0;
        __syncthreads();
        sm[t] += tmp;
        __syncthreads();
    }
    g_part[t] = sm[t] - v;
    if (t == 0) g_off[NN] = EE;
}

__global__ void scan3() {
    int i = blockIdx.x * 1024 + threadIdx.x;
    g_off[i] += g_part[blockIdx.x];
}

__global__ void csr_fill(const int* __restrict__ src, const int* __restrict__ dst,
                         const float* __restrict__ ew) {
    int e = blockIdx.x * blockDim.x + threadIdx.x;
    if (e >= EE) return;
    int d = dst[e];
    int pos = g_off[d] + atomicAdd(&g_cur[d], 1);
    g_meta[pos] = make_uint2((unsigned)src[e], __float_as_uint(ew[e]));
}

// ---------------- warp-per-node gather aggregation (no atomics, no zeroing) ----------
__global__ __launch_bounds__(256) void agg_gather(const float* __restrict__ H,
                                                  float* __restrict__ agg) {
    int node = blockIdx.x * 8 + (threadIdx.x >> 5);
    int lane = threadIdx.x & 31;
    int beg = g_off[node], end = g_off[node + 1];
    float4 acc = make_float4(0.f, 0.f, 0.f, 0.f);
    for (int b = beg; b < end; b += 32) {
        int n = min(32, end - b);
        uint2 m = (b + lane < end) ? g_meta[b + lane] : make_uint2(0u, 0u);
#pragma unroll 4
        for (int j = 0; j < n; j++) {
            int s = __shfl_sync(0xffffffffu, (int)m.x, j);
            float w = __int_as_float(__shfl_sync(0xffffffffu, (int)m.y, j));
            float4 v = __ldg(((const float4*)H) + s * 32 + lane);
            acc.x = fmaf(v.x, w, acc.x);
            acc.y = fmaf(v.y, w, acc.y);
            acc.z = fmaf(v.z, w, acc.z);
            acc.w = fmaf(v.w, w, acc.w);
        }
    }
    ((float4*)agg)[node * 32 + lane] = acc;
}

// ---------------- packed f32x2 GEMM core ----------------
__device__ __forceinline__ void mm_chunk(const float* __restrict__ sA,
                                         const float* __restrict__ sB,
                                         unsigned long long acc[8][4],
                                         int r0, int c0) {
#pragma unroll 8
    for (int k = 0; k < 64; k++) {
        ulonglong2 b01 = *(const ulonglong2*)(sB + k * 128 + c0);
        ulonglong2 b23 = *(const ulonglong2*)(sB + k * 128 + c0 + 4);
        unsigned long long bp0 = b01.x, bp1 = b01.y, bp2 = b23.x, bp3 = b23.y;
#pragma unroll
        for (int i = 0; i < 8; i++) {
            float a = sA[(r0 + i) * SA_S + k];
            unsigned long long aa;
            asm("mov.b64 %0, {%1, %1};" : "=l"(aa) : "f"(a));
            asm("fma.rn.f32x2 %0, %1, %2, %0;" : "+l"(acc[i][0]) : "l"(aa), "l"(bp0));
            asm("fma.rn.f32x2 %0, %1, %2, %0;" : "+l"(acc[i][1]) : "l"(aa), "l"(bp1));
            asm("fma.rn.f32x2 %0, %1, %2, %0;" : "+l"(acc[i][2]) : "l"(aa), "l"(bp2));
            asm("fma.rn.f32x2 %0, %1, %2, %0;" : "+l"(acc[i][3]) : "l"(aa), "l"(bp3));
        }
    }
}

__device__ __forceinline__ void load_sA(float* __restrict__ sA,
                                        const float* __restrict__ A,
                                        int base_row, int k0, int tid) {
#pragma unroll
    for (int p = 0; p < 8; p++) {
        int idx = p * 256 + tid;
        int row = idx >> 4, kq = idx & 15;
        float4 v = ((const float4*)(A + (base_row + row) * DD + k0))[kq];
        *(float4*)(sA + row * SA_S + kq * 4) = v;
    }
}

__device__ __forceinline__ void load_sA_g(float* __restrict__ sA,
                                          const float* __restrict__ A,
                                          int base_row, int k0, int tid) {
#pragma unroll
    for (int p = 0; p < 8; p++) {
        int idx = p * 256 + tid;
        int row = idx >> 4, kq = idx & 15;
        int gr = base_row + row;
        float4 v = make_float4(0.f, 0.f, 0.f, 0.f);
        if (gr >= 0 && gr < NN) v = ((const float4*)(A + gr * DD + k0))[kq];
        *(float4*)(sA + row * SA_S + kq * 4) = v;
    }
}

__device__ __forceinline__ void load_sB(float* __restrict__ sB,
                                        const float* __restrict__ W,
                                        int k0, int tid) {
#pragma unroll
    for (int p = 0; p < 8; p++) {
        int idx = p * 256 + tid;
        int kr = idx >> 5, c4 = idx & 31;
        ((float4*)(sB + kr * 128))[c4] = ((const float4*)(W + (k0 + kr) * DD))[c4];
    }
}

__device__ __forceinline__ void epilogue(unsigned long long acc[8][4],
                                         const float* __restrict__ bias,
                                         float* __restrict__ out,
                                         int base, int r0, int c0, int relu) {
    float4 bv0 = *(const float4*)(bias + c0);
    float4 bv1 = *(const float4*)(bias + c0 + 4);
    float bb[8] = {bv0.x, bv0.y, bv0.z, bv0.w, bv1.x, bv1.y, bv1.z, bv1.w};
#pragma unroll
    for (int i = 0; i < 8; i++) {
        float v[8];
#pragma unroll
        for (int j = 0; j < 4; j++) {
            float lo, hi;
            asm("mov.b64 {%0, %1}, %2;" : "=f"(lo), "=f"(hi) : "l"(acc[i][j]));
            v[2 * j] = lo; v[2 * j + 1] = hi;
        }
        float4 o0, o1;
        if (relu) {
            o0.x = fmaxf(v[0] + bb[0], 0.f); o0.y = fmaxf(v[1] + bb[1], 0.f);
            o0.z = fmaxf(v[2] + bb[2], 0.f); o0.w = fmaxf(v[3] + bb[3], 0.f);
            o1.x = fmaxf(v[4] + bb[4], 0.f); o1.y = fmaxf(v[5] + bb[5], 0.f);
            o1.z = fmaxf(v[6] + bb[6], 0.f); o1.w = fmaxf(v[7] + bb[7], 0.f);
        } else {
            o0.x = v[0] + bb[0]; o0.y = v[1] + bb[1];
            o0.z = v[2] + bb[2]; o0.w = v[3] + bb[3];
            o1.x = v[4] + bb[4]; o1.y = v[5] + bb[5];
            o1.z = v[6] + bb[6]; o1.w = v[7] + bb[7];
        }
        float* po = out + (base + r0 + i) * DD + c0;
        ((float4*)po)[0] = o0;
        ((float4*)(po + 4))[0] = o1;
    }
}

__global__ __launch_bounds__(256, 2) void gemm128_f2(
    const float* __restrict__ A, const float* __restrict__ W,
    const float* __restrict__ bias, float* __restrict__ out, int relu) {
    extern __shared__ float sm[];
    float* sA = sm;
    float* sB = sm + 128 * SA_S;
    const int tid = threadIdx.x;
    const int base = blockIdx.x * 128;
    const int ty = tid >> 4, tx = tid & 15;
    const int r0 = ty * 8, c0 = tx * 8;

    unsigned long long acc[8][4];
#pragma unroll
    for (int i = 0; i < 8; i++)
#pragma unroll
        for (int j = 0; j < 4; j++) acc[i][j] = 0ull;

#pragma unroll
    for (int kc = 0; kc < 2; kc++) {
        load_sA(sA, A, base, kc * 64, tid);
        load_sB(sB, W, kc * 64, tid);
        __syncthreads();
        mm_chunk(sA, sB, acc, r0, c0);
        __syncthreads();
    }
    epilogue(acc, bias, out, base, r0, c0, relu);
}

__global__ __launch_bounds__(256, 2) void conv128_f2(
    const float* __restrict__ X, const float* __restrict__ W3,
    const float* __restrict__ bias, float* __restrict__ out, int dil) {
    extern __shared__ float sm[];
    float* sA = sm;
    float* sB = sm + 128 * SA_S;
    const int tid = threadIdx.x;
    const int base = blockIdx.x * 128;
    const int ty = tid >> 4, tx = tid & 15;
    const int r0 = ty * 8, c0 = tx * 8;

    unsigned long long acc[8][4];
#pragma unroll
    for (int i = 0; i < 8; i++)
#pragma unroll
        for (int j = 0; j < 4; j++) acc[i][j] = 0ull;

    for (int tp = 0; tp < 3; tp++) {
        const int shift = (tp - 1) * dil;
        const float* Wt = W3 + tp * DD * DD;
#pragma unroll
        for (int kc = 0; kc < 2; kc++) {
            load_sA_g(sA, X, base + shift, kc * 64, tid);
            load_sB(sB, Wt, kc * 64, tid);
            __syncthreads();
            mm_chunk(sA, sB, acc, r0, c0);
            __syncthreads();
        }
    }
    epilogue(acc, bias, out, base, r0, c0, 0);
}

// ---------------- BN stats / apply ----------------
__global__ void bn3_stats(const float* __restrict__ c1, const float* __restrict__ c2,
                          const float* __restrict__ c3) {
    const int ch = threadIdx.x;
    const int rows = NN / 512;
    const int r0 = blockIdx.x * rows;
    float s1 = 0, q1 = 0, s2 = 0, q2 = 0, s3 = 0, q3 = 0;
    for (int r = r0; r < r0 + rows; r++) {
        int o = r * DD + ch;
        float v1 = c1[o], v2 = c2[o], v3 = c3[o];
        float x1 = fmaxf(v1, 0.f) + v2;
        float x2 = fmaxf(v2, 0.f) + v3;
        float x3 = fmaxf(v3, 0.f) + v1;
        s1 += x1; q1 = fmaf(x1, x1, q1);
        s2 += x2; q2 = fmaf(x2, x2, q2);
        s3 += x3; q3 = fmaf(x3, x3, q3);
    }
    atomicAdd(&g_stats[0 * DD + ch], s1); atomicAdd(&g_stats[1 * DD + ch], q1);
    atomicAdd(&g_stats[2 * DD + ch], s2); atomicAdd(&g_stats[3 * DD + ch], q2);
    atomicAdd(&g_stats[4 * DD + ch], s3); atomicAdd(&g_stats[5 * DD + ch], q3);
}

__global__ void bn3_apply(float* __restrict__ c1, float* __restrict__ c2,
                          float* __restrict__ c3, const float* __restrict__ g,
                          const float* __restrict__ b) {
    int idx = blockIdx.x * blockDim.x + threadIdx.x;
    int ch = idx & (DD - 1);
    float v1 = c1[idx], v2 = c2[idx], v3 = c3[idx];
    float x1 = fmaxf(v1, 0.f) + v2;
    float x2 = fmaxf(v2, 0.f) + v3;
    float x3 = fmaxf(v3, 0.f) + v1;
    const float inv = 1.f / (float)NN;
    float mu1 = g_stats[0 * DD + ch] * inv;
    float va1 = g_stats[1 * DD + ch] * inv - mu1 * mu1;
    float mu2 = g_stats[2 * DD + ch] * inv;
    float va2 = g_stats[3 * DD + ch] * inv - mu2 * mu2;
    float mu3 = g_stats[4 * DD + ch] * inv;
    float va3 = g_stats[5 * DD + ch] * inv - mu3 * mu3;
    float gg = g[ch], bb = b[ch];
    c1[idx] = (x1 - mu1) * rsqrtf(va1 + EPSV) * gg + bb;
    c2[idx] = (x2 - mu2) * rsqrtf(va2 + EPSV) * gg + bb;
    c3[idx] = (x3 - mu3) * rsqrtf(va3 + EPSV) * gg + bb;
}

__global__ void bn1_apply(float* __restrict__ x, const float* __restrict__ g,
                          const float* __restrict__ b) {
    int idx = blockIdx.x * blockDim.x + threadIdx.x;
    int ch = idx & (DD - 1);
    const float inv = 1.f / (float)NN;
    float mu = g_stats[ch] * inv;
    float va = g_stats[DD + ch] * inv - mu * mu;
    x[idx] = (x[idx] - mu) * rsqrtf(va + EPSV) * g[ch] + b[ch];
}

// ---------------- press conv fused with bn1 stats ----------------
__global__ void press_stats(const float* __restrict__ a1, const float* __restrict__ a2,
                            const float* __restrict__ a3, const float* __restrict__ pw,
                            const float* __restrict__ pb, float* __restrict__ out) {
    const int d = threadIdx.x;
    const int rows = NN / 512;
    const int r0 = blockIdx.x * rows;
    float w00 = pw[0], w01 = pw[1], w02 = pw[2];
    float w10 = pw[3], w11 = pw[4], w12 = pw[5];
    float w20 = pw[6], w21 = pw[7], w22 = pw[8];
    float pbias = pb[0];
    float s = 0.f, q = 0.f;
    for (int r = r0; r < r0 + rows; r++) {
        const float* p1 = a1 + r * DD;
        const float* p2 = a2 + r * DD;
        const float* p3 = a3 + r * DD;
        float acc = pbias;
        if (d > 0) acc += w00 * p1[d - 1] + w10 * p2[d - 1] + w20 * p3[d - 1];
        acc += w01 * p1[d] + w11 * p2[d] + w21 * p3[d];
        if (d < 127) acc += w02 * p1[d + 1] + w12 * p2[d + 1] + w22 * p3[d + 1];
        out[r * DD + d] = acc;
        s += acc; q = fmaf(acc, acc, q);
    }
    atomicAdd(&g_stats[d], s);
    atomicAdd(&g_stats[DD + d], q);
}

// ---------------- per-graph pooling (node_gid sorted) ----------------
__global__ void pool_kernel(const float* __restrict__ h2, const float* __restrict__ h3,
                            const float* __restrict__ h4, const int* __restrict__ gid) {
    const int ch = threadIdx.x;
    const int rows = NN / 512;
    const int r0 = blockIdx.x * rows;
    int cur = gid[r0];
    float s2 = 0, s3 = 0, s4 = 0;
    for (int r = r0; r < r0 + rows; r++) {
        int g = gid[r];
        if (g != cur) {
            atomicAdd(&g_hg[cur * 3 * DD + ch], s2);
            atomicAdd(&g_hg[cur * 3 * DD + DD + ch], s3);
            atomicAdd(&g_hg[cur * 3 * DD + 2 * DD + ch], s4);
            s2 = s3 = s4 = 0;
            cur = g;
        }
        int o = r * DD + ch;
        s2 += h2[o]; s3 += h3[o]; s4 += h4[o];
    }
    atomicAdd(&g_hg[cur * 3 * DD + ch], s2);
    atomicAdd(&g_hg[cur * 3 * DD + DD + ch], s3);
    atomicAdd(&g_hg[cur * 3 * DD + 2 * DD + ch], s4);
}

// ---------------- final classifier ----------------
__global__ void classify(const float* __restrict__ cl1w, const float* __restrict__ cl1b,
                         const float* __restrict__ cl2w, const float* __restrict__ cl2b,
                         float* __restrict__ out) {
    __shared__ float mid[DD];
    int t = threadIdx.x;
    for (int b = 0; b < BBG; b++) {
        float acc = cl1b[t];
        for (int k = 0; k < 3 * DD; k++) acc = fmaf(g_hg[b * 3 * DD + k], cl1w[t * 3 * DD + k], acc);
        mid[t] = acc;
        __syncthreads();
        if (t < 5) {
            float o = cl2b[t];
            for (int k = 0; k < DD; k++) o = fmaf(mid[k], cl2w[t * DD + k], o);
            out[b * 5 + t] = o;
        }
        __syncthreads();
    }
}

// ---------------- host launch ----------------
extern "C" void kernel_launch(void* const* d_in, const int* in_sizes, int n_in,
                              void* d_out, int out_size) {
    int o = (in_sizes[5] == 1) ? 6 : 5;
    const float* h   = (const float*)d_in[0];
    const float* ew  = (const float*)d_in[1];
    const int*   src = (const int*)d_in[2];
    const int*   dst = (const int*)d_in[3];
    const int*   gid = (const int*)d_in[4];
    const float* c1w = (const float*)d_in[o + 0];
    const float* c1b = (const float*)d_in[o + 1];
    const float* c2w = (const float*)d_in[o + 2];
    const float* c2b = (const float*)d_in[o + 3];
    const float* c3w = (const float*)d_in[o + 4];
    const float* c3b = (const float*)d_in[o + 5];
    const float* pw  = (const float*)d_in[o + 6];
    const float* pb  = (const float*)d_in[o + 7];
    const float* g11w = (const float*)d_in[o + 8];
    const float* g11b = (const float*)d_in[o + 9];
    const float* g12w = (const float*)d_in[o + 10];
    const float* g12b = (const float*)d_in[o + 11];
    const float* g13w = (const float*)d_in[o + 12];
    const float* g13b = (const float*)d_in[o + 13];
    const float* g2w  = (const float*)d_in[o + 14];
    const float* g2b  = (const float*)d_in[o + 15];
    const float* g3w  = (const float*)d_in[o + 16];
    const float* g3b  = (const float*)d_in[o + 17];
    const float* g4w  = (const float*)d_in[o + 18];
    const float* g4b  = (const float*)d_in[o + 19];
    const float* bng  = (const float*)d_in[o + 20];
    const float* bnb  = (const float*)d_in[o + 21];
    const float* cl1w = (const float*)d_in[o + 22];
    const float* cl1b = (const float*)d_in[o + 23];
    const float* cl2w = (const float*)d_in[o + 24];
    const float* cl2b = (const float*)d_in[o + 25];
    float* out = (float*)d_out;

    float *A, *B, *C, *a1, *a2, *a3, *agg, *convw;
    cudaGetSymbolAddress((void**)&A, g_A);
    cudaGetSymbolAddress((void**)&B, g_B);
    cudaGetSymbolAddress((void**)&C, g_C);
    cudaGetSymbolAddress((void**)&a1, g_a1);
    cudaGetSymbolAddress((void**)&a2, g_a2);
    cudaGetSymbolAddress((void**)&a3, g_a3);
    cudaGetSymbolAddress((void**)&agg, g_agg);
    cudaGetSymbolAddress((void**)&convw, g_convw);

    const int MM_SMEM = (128 * SA_S + 64 * 128) * 4;
    cudaFuncSetAttribute(gemm128_f2, cudaFuncAttributeMaxDynamicSharedMemorySize, MM_SMEM);
    cudaFuncSetAttribute(conv128_f2, cudaFuncAttributeMaxDynamicSharedMemorySize, MM_SMEM);

    // ---- CSR build (once per launch, reused by all 6 graph convs) ----
    zero_degcur<<<NN / 512, 512>>>();
    hist_dst<<<EE / 512, 512>>>(dst);
    scan1<<<128, 1024>>>();
    scan2<<<1, 128>>>();
    scan3<<<128, 1024>>>();
    csr_fill<<<EE / 512, 512>>>(src, dst, ew);

    // ---- dense front-end ----
    prep_conv_w<<<(3 * DD * DD + 255) / 256, 256>>>(c1w, c2w, c3w);
    conv128_f2<<<NN / 128, 256, MM_SMEM>>>(h, convw + 0 * 3 * DD * DD, c1b, A, 1);
    conv128_f2<<<NN / 128, 256, MM_SMEM>>>(h, convw + 1 * 3 * DD * DD, c2b, B, 2);
    conv128_f2<<<NN / 128, 256, MM_SMEM>>>(h, convw + 2 * 3 * DD * DD, c3b, C, 3);

    zero_stats_hg<<<24, 256>>>();
    bn3_stats<<<512, DD>>>(A, B, C);
    bn3_apply<<<NN * DD / 256, 256>>>(A, B, C, bng, bnb);

#define GCONV(IN, W, BIAS, OUT)                                        \
    agg_gather<<<NN / 8, 256>>>(IN, agg);                              \
    gemm128_f2<<<NN / 128, 256, MM_SMEM>>>(agg, W, BIAS, OUT, 1);

    GCONV(A, g11w, g11b, a1)
    GCONV(B, g12w, g12b, a2)
    GCONV(C, g13w, g13b, a3)

    zero_stats_hg<<<24, 256>>>();
    press_stats<<<512, DD>>>(a1, a2, a3, pw, pb, A);
    bn1_apply<<<NN * DD / 256, 256>>>(A, bng, bnb);

    GCONV(A, g2w, g2b, B)   // ac_h2
    GCONV(B, g3w, g3b, C)   // ac_h3
    GCONV(C, g4w, g4b, a1)  // ac_h4

    pool_kernel<<<512, DD>>>(B, C, a1, gid);
    classify<<<1, DD>>>(cl1w, cl1b, cl2w, cl2b, out);
#undef GCONV
}

// round 7
// speedup vs baseline: 1.2497x; 1.0143x over previous
#include <cuda_runtime.h>
#include <cstdint>

#define NN 131072
#define DD 128
#define EE 2097152
#define BBG 16
#define EPSV 1e-5f

#define AST 132   // sA stride (floats): bank = 4g+t bijective
#define WST 136   // sW stride (floats): bank = 8t+g bijective

// ---------------- device scratch (no allocations allowed) ----------------
__device__ float g_A[NN * DD];
__device__ float g_B[NN * DD];
__device__ float g_C[NN * DD];
__device__ float g_a1[NN * DD];
__device__ float g_a2[NN * DD];
__device__ float g_a3[NN * DD];
__device__ float g_agg[NN * DD];
__device__ float g_convw[3 * 3 * DD * DD];
__device__ float g_stats[12 * DD];
__device__ float g_hg[BBG * 3 * DD];
// CSR scratch
__device__ uint2 g_meta[EE];
__device__ int g_deg[NN];
__device__ int g_off[NN + 1];
__device__ int g_cur[NN];
__device__ int g_part[128];

// ---------------- small kernels ----------------
__global__ void prep_conv_w(const float* __restrict__ w1,
                            const float* __restrict__ w2,
                            const float* __restrict__ w3) {
    int idx = blockIdx.x * blockDim.x + threadIdx.x;
    if (idx >= 3 * DD * DD) return;
    int o = idx % DD;
    int i = (idx / DD) % DD;
    int t = idx / (DD * DD);
    g_convw[((0 * 3 + t) * DD + i) * DD + o] = w1[(o * DD + i) * 3 + t];
    g_convw[((1 * 3 + t) * DD + i) * DD + o] = w2[(o * DD + i) * 3 + t];
    g_convw[((2 * 3 + t) * DD + i) * DD + o] = w3[(o * DD + i) * 3 + t];
}

__global__ void zero_stats_hg() {
    int i = blockIdx.x * blockDim.x + threadIdx.x;
    if (i < 12 * DD) g_stats[i] = 0.f;
    if (i < BBG * 3 * DD) g_hg[i] = 0.f;
}

// ---------------- CSR build ----------------
__global__ void zero_degcur() {
    int i = blockIdx.x * blockDim.x + threadIdx.x;
    if (i < NN) { g_deg[i] = 0; g_cur[i] = 0; }
}

__global__ void hist_dst(const int* __restrict__ dst) {
    int e = blockIdx.x * blockDim.x + threadIdx.x;
    if (e < EE) atomicAdd(&g_deg[dst[e]], 1);
}

__global__ void scan1() {
    __shared__ int sm[1024];
    int t = threadIdx.x;
    int i = blockIdx.x * 1024 + t;
    int v = g_deg[i];
    sm[t] = v;
    __syncthreads();
    for (int d = 1; d < 1024; d <<= 1) {
        int tmp = (t >= d) ? sm[t - d] : 0;
        __syncthreads();
        sm[t] += tmp;
        __syncthreads();
    }
    g_off[i] = sm[t] - v;
    if (t == 1023) g_part[blockIdx.x] = sm[1023];
}

__global__ void scan2() {
    __shared__ int sm[128];
    int t = threadIdx.x;
    int v = g_part[t];
    sm[t] = v;
    __syncthreads();
    for (int d = 1; d < 128; d <<= 1) {
        int tmp = (t >= d) ? sm[t - d] : 0;
        __syncthreads();
        sm[t] += tmp;
        __syncthreads();
    }
    g_part[t] = sm[t] - v;
    if (t == 0) g_off[NN] = EE;
}

__global__ void scan3() {
    int i = blockIdx.x * 1024 + threadIdx.x;
    g_off[i] += g_part[blockIdx.x];
}

__global__ void csr_fill(const int* __restrict__ src, const int* __restrict__ dst,
                         const float* __restrict__ ew) {
    int e = blockIdx.x * blockDim.x + threadIdx.x;
    if (e >= EE) return;
    int d = dst[e];
    int pos = g_off[d] + atomicAdd(&g_cur[d], 1);
    g_meta[pos] = make_uint2((unsigned)src[e], __float_as_uint(ew[e]));
}

// ---------------- warp-per-node gather aggregation ----------------
__global__ __launch_bounds__(256) void agg_gather(const float* __restrict__ H,
                                                  float* __restrict__ agg) {
    int node = blockIdx.x * 8 + (threadIdx.x >> 5);
    int lane = threadIdx.x & 31;
    int beg = g_off[node], end = g_off[node + 1];
    float4 acc = make_float4(0.f, 0.f, 0.f, 0.f);
    for (int b = beg; b < end; b += 32) {
        int n = min(32, end - b);
        uint2 m = (b + lane < end) ? g_meta[b + lane] : make_uint2(0u, 0u);
#pragma unroll 4
        for (int j = 0; j < n; j++) {
            int s = __shfl_sync(0xffffffffu, (int)m.x, j);
            float w = __int_as_float(__shfl_sync(0xffffffffu, (int)m.y, j));
            float4 v = __ldg(((const float4*)H) + s * 32 + lane);
            acc.x = fmaf(v.x, w, acc.x);
            acc.y = fmaf(v.y, w, acc.y);
            acc.z = fmaf(v.z, w, acc.z);
            acc.w = fmaf(v.w, w, acc.w);
        }
    }
    ((float4*)agg)[node * 32 + lane] = acc;
}

// ---------------- TF32 mma helpers ----------------
__device__ __forceinline__ uint32_t f2tf(float x) {
    uint32_t r;
    asm("cvt.rna.tf32.f32 %0, %1;" : "=r"(r) : "f"(x));
    return r;
}

#define MMA8(c, A0, A1, A2, A3, B0, B1)                                        \
    asm("mma.sync.aligned.m16n8k8.row.col.f32.tf32.tf32.f32 "                  \
        "{%0,%1,%2,%3},{%4,%5,%6,%7},{%8,%9},{%0,%1,%2,%3};"                   \
        : "+f"((c)[0]), "+f"((c)[1]), "+f"((c)[2]), "+f"((c)[3])               \
        : "r"(A0), "r"(A1), "r"(A2), "r"(A3), "r"(B0), "r"(B1))

// ---- core compute over staged sA[128][AST], sW[128][WST]; 3xTF32 split ----
__device__ __forceinline__ void mma_mainloop(const float* __restrict__ sA,
                                             const float* __restrict__ sW,
                                             float acc[2][8][4],
                                             int mrow, int ncol, int g, int t) {
#pragma unroll 4
    for (int kk = 0; kk < 128; kk += 8) {
        uint32_t ahi[2][4], alo[2][4];
#pragma unroll
        for (int m = 0; m < 2; m++) {
            int r0 = mrow + m * 16 + g;
            float av0 = sA[r0 * AST + kk + t];
            float av1 = sA[(r0 + 8) * AST + kk + t];
            float av2 = sA[r0 * AST + kk + t + 4];
            float av3 = sA[(r0 + 8) * AST + kk + t + 4];
            ahi[m][0] = f2tf(av0); alo[m][0] = f2tf(av0 - __uint_as_float(ahi[m][0]));
            ahi[m][1] = f2tf(av1); alo[m][1] = f2tf(av1 - __uint_as_float(ahi[m][1]));
            ahi[m][2] = f2tf(av2); alo[m][2] = f2tf(av2 - __uint_as_float(ahi[m][2]));
            ahi[m][3] = f2tf(av3); alo[m][3] = f2tf(av3 - __uint_as_float(ahi[m][3]));
        }
#pragma unroll
        for (int ct = 0; ct < 8; ct++) {
            float b0f = sW[(kk + t) * WST + ncol + ct * 8 + g];
            float b1f = sW[(kk + t + 4) * WST + ncol + ct * 8 + g];
            uint32_t bh0 = f2tf(b0f), bl0 = f2tf(b0f - __uint_as_float(bh0));
            uint32_t bh1 = f2tf(b1f), bl1 = f2tf(b1f - __uint_as_float(bh1));
#pragma unroll
            for (int m = 0; m < 2; m++) {
                MMA8(acc[m][ct], ahi[m][0], ahi[m][1], ahi[m][2], ahi[m][3], bh0, bh1);
                MMA8(acc[m][ct], ahi[m][0], ahi[m][1], ahi[m][2], ahi[m][3], bl0, bl1);
                MMA8(acc[m][ct], alo[m][0], alo[m][1], alo[m][2], alo[m][3], bh0, bh1);
            }
        }
    }
}

__device__ __forceinline__ void mma_epilogue(float acc[2][8][4],
                                             const float* __restrict__ bias,
                                             float* __restrict__ out,
                                             int base, int mrow, int ncol,
                                             int g, int t, int relu) {
#pragma unroll
    for (int m = 0; m < 2; m++) {
#pragma unroll
        for (int ct = 0; ct < 8; ct++) {
            int row = base + mrow + m * 16 + g;
            int col = ncol + ct * 8 + 2 * t;
            float b0 = bias[col], b1 = bias[col + 1];
            float v0 = acc[m][ct][0] + b0, v1 = acc[m][ct][1] + b1;
            float v2 = acc[m][ct][2] + b0, v3 = acc[m][ct][3] + b1;
            if (relu) {
                v0 = fmaxf(v0, 0.f); v1 = fmaxf(v1, 0.f);
                v2 = fmaxf(v2, 0.f); v3 = fmaxf(v3, 0.f);
            }
            *(float2*)(out + row * DD + col) = make_float2(v0, v1);
            *(float2*)(out + (row + 8) * DD + col) = make_float2(v2, v3);
        }
    }
}

__device__ __forceinline__ void load_sW_full(float* __restrict__ sW,
                                             const float* __restrict__ W, int tid) {
#pragma unroll
    for (int p = 0; p < 16; p++) {
        int idx = p * 256 + tid;
        int row = idx >> 5, c4 = idx & 31;
        float4 v = ((const float4*)(W + row * DD))[c4];
        *(float4*)(sW + row * WST + c4 * 4) = v;
    }
}

// ---------------- tensor-core GEMM: out = [relu](A @ W + b) ----------------
__global__ __launch_bounds__(256) void gemm_mma(
    const float* __restrict__ A, const float* __restrict__ W,
    const float* __restrict__ bias, float* __restrict__ out, int relu) {
    extern __shared__ float sm[];
    float* sA = sm;                 // [128][AST]
    float* sW = sm + 128 * AST;     // [128][WST]
    const int tid = threadIdx.x;
    const int base = blockIdx.x * 128;

#pragma unroll
    for (int p = 0; p < 16; p++) {
        int idx = p * 256 + tid;
        int row = idx >> 5, c4 = idx & 31;
        float4 v = ((const float4*)(A + (base + row) * DD))[c4];
        *(float4*)(sA + row * AST + c4 * 4) = v;
    }
    load_sW_full(sW, W, tid);
    __syncthreads();

    const int w = tid >> 5, lane = tid & 31, g = lane >> 2, t = lane & 3;
    const int mrow = (w & 3) * 32, ncol = (w >> 2) * 64;

    float acc[2][8][4];
#pragma unroll
    for (int m = 0; m < 2; m++)
#pragma unroll
        for (int c = 0; c < 8; c++)
#pragma unroll
            for (int j = 0; j < 4; j++) acc[m][c][j] = 0.f;

    mma_mainloop(sA, sW, acc, mrow, ncol, g, t);
    mma_epilogue(acc, bias, out, base, mrow, ncol, g, t, relu);
}

// ---------------- tensor-core dilated conv (3 shifted GEMMs accumulated) ----------
__global__ __launch_bounds__(256) void conv_mma(
    const float* __restrict__ X, const float* __restrict__ W3,
    const float* __restrict__ bias, float* __restrict__ out, int dil) {
    extern __shared__ float sm[];
    float* sA = sm;
    float* sW = sm + 128 * AST;
    const int tid = threadIdx.x;
    const int base = blockIdx.x * 128;
    const int w = tid >> 5, lane = tid & 31, g = lane >> 2, t = lane & 3;
    const int mrow = (w & 3) * 32, ncol = (w >> 2) * 64;

    float acc[2][8][4];
#pragma unroll
    for (int m = 0; m < 2; m++)
#pragma unroll
        for (int c = 0; c < 8; c++)
#pragma unroll
            for (int j = 0; j < 4; j++) acc[m][c][j] = 0.f;

    for (int tp = 0; tp < 3; tp++) {
        const int shift = (tp - 1) * dil;
        __syncthreads();
#pragma unroll
        for (int p = 0; p < 16; p++) {
            int idx = p * 256 + tid;
            int row = idx >> 5, c4 = idx & 31;
            int gr = base + shift + row;
            float4 v = make_float4(0.f, 0.f, 0.f, 0.f);
            if (gr >= 0 && gr < NN) v = ((const float4*)(X + gr * DD))[c4];
            *(float4*)(sA + row * AST + c4 * 4) = v;
        }
        load_sW_full(sW, W3 + tp * DD * DD, tid);
        __syncthreads();
        mma_mainloop(sA, sW, acc, mrow, ncol, g, t);
    }
    mma_epilogue(acc, bias, out, base, mrow, ncol, g, t, 0);
}

// ---------------- BN stats / apply ----------------
__global__ void bn3_stats(const float* __restrict__ c1, const float* __restrict__ c2,
                          const float* __restrict__ c3) {
    const int ch = threadIdx.x;
    const int rows = NN / 512;
    const int r0 = blockIdx.x * rows;
    float s1 = 0, q1 = 0, s2 = 0, q2 = 0, s3 = 0, q3 = 0;
    for (int r = r0; r < r0 + rows; r++) {
        int o = r * DD + ch;
        float v1 = c1[o], v2 = c2[o], v3 = c3[o];
        float x1 = fmaxf(v1, 0.f) + v2;
        float x2 = fmaxf(v2, 0.f) + v3;
        float x3 = fmaxf(v3, 0.f) + v1;
        s1 += x1; q1 = fmaf(x1, x1, q1);
        s2 += x2; q2 = fmaf(x2, x2, q2);
        s3 += x3; q3 = fmaf(x3, x3, q3);
    }
    atomicAdd(&g_stats[0 * DD + ch], s1); atomicAdd(&g_stats[1 * DD + ch], q1);
    atomicAdd(&g_stats[2 * DD + ch], s2); atomicAdd(&g_stats[3 * DD + ch], q2);
    atomicAdd(&g_stats[4 * DD + ch], s3); atomicAdd(&g_stats[5 * DD + ch], q3);
}

__global__ void bn3_apply(float* __restrict__ c1, float* __restrict__ c2,
                          float* __restrict__ c3, const float* __restrict__ g,
                          const float* __restrict__ b) {
    int idx = blockIdx.x * blockDim.x + threadIdx.x;
    int ch = idx & (DD - 1);
    float v1 = c1[idx], v2 = c2[idx], v3 = c3[idx];
    float x1 = fmaxf(v1, 0.f) + v2;
    float x2 = fmaxf(v2, 0.f) + v3;
    float x3 = fmaxf(v3, 0.f) + v1;
    const float inv = 1.f / (float)NN;
    float mu1 = g_stats[0 * DD + ch] * inv;
    float va1 = g_stats[1 * DD + ch] * inv - mu1 * mu1;
    float mu2 = g_stats[2 * DD + ch] * inv;
    float va2 = g_stats[3 * DD + ch] * inv - mu2 * mu2;
    float mu3 = g_stats[4 * DD + ch] * inv;
    float va3 = g_stats[5 * DD + ch] * inv - mu3 * mu3;
    float gg = g[ch], bb = b[ch];
    c1[idx] = (x1 - mu1) * rsqrtf(va1 + EPSV) * gg + bb;
    c2[idx] = (x2 - mu2) * rsqrtf(va2 + EPSV) * gg + bb;
    c3[idx] = (x3 - mu3) * rsqrtf(va3 + EPSV) * gg + bb;
}

__global__ void bn1_apply(float* __restrict__ x, const float* __restrict__ g,
                          const float* __restrict__ b) {
    int idx = blockIdx.x * blockDim.x + threadIdx.x;
    int ch = idx & (DD - 1);
    const float inv = 1.f / (float)NN;
    float mu = g_stats[ch] * inv;
    float va = g_stats[DD + ch] * inv - mu * mu;
    x[idx] = (x[idx] - mu) * rsqrtf(va + EPSV) * g[ch] + b[ch];
}

// ---------------- press conv fused with bn1 stats ----------------
__global__ void press_stats(const float* __restrict__ a1, const float* __restrict__ a2,
                            const float* __restrict__ a3, const float* __restrict__ pw,
                            const float* __restrict__ pb, float* __restrict__ out) {
    const int d = threadIdx.x;
    const int rows = NN / 512;
    const int r0 = blockIdx.x * rows;
    float w00 = pw[0], w01 = pw[1], w02 = pw[2];
    float w10 = pw[3], w11 = pw[4], w12 = pw[5];
    float w20 = pw[6], w21 = pw[7], w22 = pw[8];
    float pbias = pb[0];
    float s = 0.f, q = 0.f;
    for (int r = r0; r < r0 + rows; r++) {
        const float* p1 = a1 + r * DD;
        const float* p2 = a2 + r * DD;
        const float* p3 = a3 + r * DD;
        float acc = pbias;
        if (d > 0) acc += w00 * p1[d - 1] + w10 * p2[d - 1] + w20 * p3[d - 1];
        acc += w01 * p1[d] + w11 * p2[d] + w21 * p3[d];
        if (d < 127) acc += w02 * p1[d + 1] + w12 * p2[d + 1] + w22 * p3[d + 1];
        out[r * DD + d] = acc;
        s += acc; q = fmaf(acc, acc, q);
    }
    atomicAdd(&g_stats[d], s);
    atomicAdd(&g_stats[DD + d], q);
}

// ---------------- per-graph pooling ----------------
__global__ void pool_kernel(const float* __restrict__ h2, const float* __restrict__ h3,
                            const float* __restrict__ h4, const int* __restrict__ gid) {
    const int ch = threadIdx.x;
    const int rows = NN / 512;
    const int r0 = blockIdx.x * rows;
    int cur = gid[r0];
    float s2 = 0, s3 = 0, s4 = 0;
    for (int r = r0; r < r0 + rows; r++) {
        int g = gid[r];
        if (g != cur) {
            atomicAdd(&g_hg[cur * 3 * DD + ch], s2);
            atomicAdd(&g_hg[cur * 3 * DD + DD + ch], s3);
            atomicAdd(&g_hg[cur * 3 * DD + 2 * DD + ch], s4);
            s2 = s3 = s4 = 0;
            cur = g;
        }
        int o = r * DD + ch;
        s2 += h2[o]; s3 += h3[o]; s4 += h4[o];
    }
    atomicAdd(&g_hg[cur * 3 * DD + ch], s2);
    atomicAdd(&g_hg[cur * 3 * DD + DD + ch], s3);
    atomicAdd(&g_hg[cur * 3 * DD + 2 * DD + ch], s4);
}

// ---------------- final classifier ----------------
__global__ void classify(const float* __restrict__ cl1w, const float* __restrict__ cl1b,
                         const float* __restrict__ cl2w, const float* __restrict__ cl2b,
                         float* __restrict__ out) {
    __shared__ float mid[DD];
    int t = threadIdx.x;
    for (int b = 0; b < BBG; b++) {
        float acc = cl1b[t];
        for (int k = 0; k < 3 * DD; k++) acc = fmaf(g_hg[b * 3 * DD + k], cl1w[t * 3 * DD + k], acc);
        mid[t] = acc;
        __syncthreads();
        if (t < 5) {
            float o = cl2b[t];
            for (int k = 0; k < DD; k++) o = fmaf(mid[k], cl2w[t * DD + k], o);
            out[b * 5 + t] = o;
        }
        __syncthreads();
    }
}

// ---------------- host launch ----------------
extern "C" void kernel_launch(void* const* d_in, const int* in_sizes, int n_in,
                              void* d_out, int out_size) {
    int o = (in_sizes[5] == 1) ? 6 : 5;
    const float* h   = (const float*)d_in[0];
    const float* ew  = (const float*)d_in[1];
    const int*   src = (const int*)d_in[2];
    const int*   dst = (const int*)d_in[3];
    const int*   gid = (const int*)d_in[4];
    const float* c1w = (const float*)d_in[o + 0];
    const float* c1b = (const float*)d_in[o + 1];
    const float* c2w = (const float*)d_in[o + 2];
    const float* c2b = (const float*)d_in[o + 3];
    const float* c3w = (const float*)d_in[o + 4];
    const float* c3b = (const float*)d_in[o + 5];
    const float* pw  = (const float*)d_in[o + 6];
    const float* pb  = (const float*)d_in[o + 7];
    const float* g11w = (const float*)d_in[o + 8];
    const float* g11b = (const float*)d_in[o + 9];
    const float* g12w = (const float*)d_in[o + 10];
    const float* g12b = (const float*)d_in[o + 11];
    const float* g13w = (const float*)d_in[o + 12];
    const float* g13b = (const float*)d_in[o + 13];
    const float* g2w  = (const float*)d_in[o + 14];
    const float* g2b  = (const float*)d_in[o + 15];
    const float* g3w  = (const float*)d_in[o + 16];
    const float* g3b  = (const float*)d_in[o + 17];
    const float* g4w  = (const float*)d_in[o + 18];
    const float* g4b  = (const float*)d_in[o + 19];
    const float* bng  = (const float*)d_in[o + 20];
    const float* bnb  = (const float*)d_in[o + 21];
    const float* cl1w = (const float*)d_in[o + 22];
    const float* cl1b = (const float*)d_in[o + 23];
    const float* cl2w = (const float*)d_in[o + 24];
    const float* cl2b = (const float*)d_in[o + 25];
    float* out = (float*)d_out;

    float *A, *B, *C, *a1, *a2, *a3, *agg, *convw;
    cudaGetSymbolAddress((void**)&A, g_A);
    cudaGetSymbolAddress((void**)&B, g_B);
    cudaGetSymbolAddress((void**)&C, g_C);
    cudaGetSymbolAddress((void**)&a1, g_a1);
    cudaGetSymbolAddress((void**)&a2, g_a2);
    cudaGetSymbolAddress((void**)&a3, g_a3);
    cudaGetSymbolAddress((void**)&agg, g_agg);
    cudaGetSymbolAddress((void**)&convw, g_convw);

    const int MM_SMEM = (128 * AST + 128 * WST) * 4;  // 137216 B
    cudaFuncSetAttribute(gemm_mma, cudaFuncAttributeMaxDynamicSharedMemorySize, MM_SMEM);
    cudaFuncSetAttribute(conv_mma, cudaFuncAttributeMaxDynamicSharedMemorySize, MM_SMEM);

    // ---- CSR build (once per launch, reused by all 6 graph convs) ----
    zero_degcur<<<NN / 512, 512>>>();
    hist_dst<<<EE / 512, 512>>>(dst);
    scan1<<<128, 1024>>>();
    scan2<<<1, 128>>>();
    scan3<<<128, 1024>>>();
    csr_fill<<<EE / 512, 512>>>(src, dst, ew);

    // ---- dense front-end (tensor cores, 3xTF32) ----
    prep_conv_w<<<(3 * DD * DD + 255) / 256, 256>>>(c1w, c2w, c3w);
    conv_mma<<<NN / 128, 256, MM_SMEM>>>(h, convw + 0 * 3 * DD * DD, c1b, A, 1);
    conv_mma<<<NN / 128, 256, MM_SMEM>>>(h, convw + 1 * 3 * DD * DD, c2b, B, 2);
    conv_mma<<<NN / 128, 256, MM_SMEM>>>(h, convw + 2 * 3 * DD * DD, c3b, C, 3);

    zero_stats_hg<<<24, 256>>>();
    bn3_stats<<<512, DD>>>(A, B, C);
    bn3_apply<<<NN * DD / 256, 256>>>(A, B, C, bng, bnb);

#define GCONV(IN, W, BIAS, OUT)                                        \
    agg_gather<<<NN / 8, 256>>>(IN, agg);                              \
    gemm_mma<<<NN / 128, 256, MM_SMEM>>>(agg, W, BIAS, OUT, 1);

    GCONV(A, g11w, g11b, a1)
    GCONV(B, g12w, g12b, a2)
    GCONV(C, g13w, g13b, a3)

    zero_stats_hg<<<24, 256>>>();
    press_stats<<<512, DD>>>(a1, a2, a3, pw, pb, A);
    bn1_apply<<<NN * DD / 256, 256>>>(A, bng, bnb);

    GCONV(A, g2w, g2b, B)   // ac_h2
    GCONV(B, g3w, g3b, C)   // ac_h3
    GCONV(C, g4w, g4b, a1)  // ac_h4

    pool_kernel<<<512, DD>>>(B, C, a1, gid);
    classify<<<1, DD>>>(cl1w, cl1b, cl2w, cl2b, out);
#undef GCONV
}

// round 8
// speedup vs baseline: 1.2950x; 1.0363x over previous
#include <cuda_runtime.h>
#include <cstdint>

#define NN 131072
#define DD 128
#define EE 2097152
#define BBG 16
#define EPSV 1e-5f

#define AST 68    // sA stride (floats), K-chunk = 64
#define WST2 132  // sW stride (uint2), 128 cols + pad

// ---------------- device scratch (no allocations allowed) ----------------
__device__ float g_A[NN * DD];
__device__ float g_B[NN * DD];
__device__ float g_C[NN * DD];
__device__ float g_a1[NN * DD];
__device__ float g_a2[NN * DD];
__device__ float g_a3[NN * DD];
__device__ float g_agg[NN * DD];
__device__ float g_convw[9 * DD * DD];       // [conv*3+tap][in][out] fp32
__device__ uint2 g_wsplit[15 * DD * DD];     // tf32 (hi,lo): 0-8 conv taps, 9-14 gconv
__device__ float g_stats[12 * DD];
__device__ float g_hg[BBG * 3 * DD];
// CSR scratch
__device__ uint2 g_meta[EE];
__device__ int g_deg[NN];
__device__ int g_off[NN + 1];
__device__ int g_cur[NN];
__device__ int g_part[128];

// ---------------- TF32 helpers ----------------
__device__ __forceinline__ uint32_t f2tf(float x) {
    uint32_t r;
    asm("cvt.rna.tf32.f32 %0, %1;" : "=r"(r) : "f"(x));
    return r;
}

#define MMA8(c, A0, A1, A2, A3, B0, B1)                                        \
    asm("mma.sync.aligned.m16n8k8.row.col.f32.tf32.tf32.f32 "                  \
        "{%0,%1,%2,%3},{%4,%5,%6,%7},{%8,%9},{%0,%1,%2,%3};"                   \
        : "+f"((c)[0]), "+f"((c)[1]), "+f"((c)[2]), "+f"((c)[3])               \
        : "r"(A0), "r"(A1), "r"(A2), "r"(A3), "r"(B0), "r"(B1))

// ---------------- weight prep ----------------
__global__ void prep_conv_w(const float* __restrict__ w1,
                            const float* __restrict__ w2,
                            const float* __restrict__ w3) {
    int idx = blockIdx.x * blockDim.x + threadIdx.x;
    if (idx >= 3 * DD * DD) return;
    int o = idx % DD;
    int i = (idx / DD) % DD;
    int t = idx / (DD * DD);
    g_convw[((0 * 3 + t) * DD + i) * DD + o] = w1[(o * DD + i) * 3 + t];
    g_convw[((1 * 3 + t) * DD + i) * DD + o] = w2[(o * DD + i) * 3 + t];
    g_convw[((2 * 3 + t) * DD + i) * DD + o] = w3[(o * DD + i) * 3 + t];
}

__global__ void prep_wsplit(const float* __restrict__ p0, const float* __restrict__ p1,
                            const float* __restrict__ p2, const float* __restrict__ p3,
                            const float* __restrict__ p4, const float* __restrict__ p5) {
    int idx = blockIdx.x * blockDim.x + threadIdx.x;
    if (idx >= 15 * DD * DD) return;
    int m = idx >> 14;
    int e = idx & 16383;
    float v;
    if (m < 9) {
        v = g_convw[idx];
    } else {
        const float* p;
        switch (m - 9) {
            case 0: p = p0; break;
            case 1: p = p1; break;
            case 2: p = p2; break;
            case 3: p = p3; break;
            case 4: p = p4; break;
            default: p = p5; break;
        }
        v = p[e];
    }
    uint32_t hi = f2tf(v);
    uint32_t lo = f2tf(v - __uint_as_float(hi));
    g_wsplit[idx] = make_uint2(hi, lo);
}

__global__ void zero_stats_hg() {
    int i = blockIdx.x * blockDim.x + threadIdx.x;
    if (i < 12 * DD) g_stats[i] = 0.f;
    if (i < BBG * 3 * DD) g_hg[i] = 0.f;
}

// ---------------- CSR build ----------------
__global__ void zero_degcur() {
    int i = blockIdx.x * blockDim.x + threadIdx.x;
    if (i < NN) { g_deg[i] = 0; g_cur[i] = 0; }
}

__global__ void hist_dst(const int* __restrict__ dst) {
    int e = blockIdx.x * blockDim.x + threadIdx.x;
    if (e < EE) atomicAdd(&g_deg[dst[e]], 1);
}

__global__ void scan1() {
    __shared__ int sm[1024];
    int t = threadIdx.x;
    int i = blockIdx.x * 1024 + t;
    int v = g_deg[i];
    sm[t] = v;
    __syncthreads();
    for (int d = 1; d < 1024; d <<= 1) {
        int tmp = (t >= d) ? sm[t - d] : 0;
        __syncthreads();
        sm[t] += tmp;
        __syncthreads();
    }
    g_off[i] = sm[t] - v;
    if (t == 1023) g_part[blockIdx.x] = sm[1023];
}

__global__ void scan2() {
    __shared__ int sm[128];
    int t = threadIdx.x;
    int v = g_part[t];
    sm[t] = v;
    __syncthreads();
    for (int d = 1; d < 128; d <<= 1) {
        int tmp = (t >= d) ? sm[t - d] : 0;
        __syncthreads();
        sm[t] += tmp;
        __syncthreads();
    }
    g_part[t] = sm[t] - v;
    if (t == 0) g_off[NN] = EE;
}

__global__ void scan3() {
    int i = blockIdx.x * 1024 + threadIdx.x;
    g_off[i] += g_part[blockIdx.x];
}

__global__ void csr_fill(const int* __restrict__ src, const int* __restrict__ dst,
                         const float* __restrict__ ew) {
    int e = blockIdx.x * blockDim.x + threadIdx.x;
    if (e >= EE) return;
    int d = dst[e];
    int pos = g_off[d] + atomicAdd(&g_cur[d], 1);
    g_meta[pos] = make_uint2((unsigned)src[e], __float_as_uint(ew[e]));
}

// ---------------- warp-per-node gather aggregation ----------------
__global__ __launch_bounds__(256) void agg_gather(const float* __restrict__ H,
                                                  float* __restrict__ agg) {
    int node = blockIdx.x * 8 + (threadIdx.x >> 5);
    int lane = threadIdx.x & 31;
    int beg = g_off[node], end = g_off[node + 1];
    float4 acc = make_float4(0.f, 0.f, 0.f, 0.f);
    for (int b = beg; b < end; b += 32) {
        int n = min(32, end - b);
        uint2 m = (b + lane < end) ? g_meta[b + lane] : make_uint2(0u, 0u);
#pragma unroll 4
        for (int j = 0; j < n; j++) {
            int s = __shfl_sync(0xffffffffu, (int)m.x, j);
            float w = __int_as_float(__shfl_sync(0xffffffffu, (int)m.y, j));
            float4 v = __ldg(((const float4*)H) + s * 32 + lane);
            acc.x = fmaf(v.x, w, acc.x);
            acc.y = fmaf(v.y, w, acc.y);
            acc.z = fmaf(v.z, w, acc.z);
            acc.w = fmaf(v.w, w, acc.w);
        }
    }
    ((float4*)agg)[node * 32 + lane] = acc;
}

// ---------------- MMA staging + mainloop (K-chunk = 64) ----------------
__device__ __forceinline__ void load_sA_chunk(float* __restrict__ sA,
                                              const float* __restrict__ A,
                                              int base_row, int k0, int tid) {
#pragma unroll
    for (int p = 0; p < 8; p++) {
        int idx = p * 256 + tid;
        int row = idx >> 4, kq = idx & 15;
        float4 v = ((const float4*)(A + (base_row + row) * DD + k0))[kq];
        *(float4*)(sA + row * AST + kq * 4) = v;
    }
}

__device__ __forceinline__ void load_sA_chunk_g(float* __restrict__ sA,
                                                const float* __restrict__ A,
                                                int base_row, int k0, int tid) {
#pragma unroll
    for (int p = 0; p < 8; p++) {
        int idx = p * 256 + tid;
        int row = idx >> 4, kq = idx & 15;
        int gr = base_row + row;
        float4 v = make_float4(0.f, 0.f, 0.f, 0.f);
        if (gr >= 0 && gr < NN) v = ((const float4*)(A + gr * DD + k0))[kq];
        *(float4*)(sA + row * AST + kq * 4) = v;
    }
}

__device__ __forceinline__ void load_sW_chunk(uint2* __restrict__ sW2,
                                              const uint2* __restrict__ Wsplit,
                                              int k0, int tid) {
#pragma unroll
    for (int p = 0; p < 16; p++) {
        int idx = p * 256 + tid;         // over 4096 uint4
        int row = idx >> 6, cp = idx & 63;
        ((uint4*)(sW2 + row * WST2))[cp] =
            ((const uint4*)(Wsplit + (k0 + row) * DD))[cp];
    }
}

__device__ __forceinline__ void mma_chunk(const float* __restrict__ sA,
                                          const uint2* __restrict__ sW2,
                                          float acc[2][8][4],
                                          int mrow, int ncol, int g, int t) {
#pragma unroll 2
    for (int kk = 0; kk < 64; kk += 8) {
        uint32_t ahi[2][4], alo[2][4];
#pragma unroll
        for (int m = 0; m < 2; m++) {
            int r0 = mrow + m * 16 + g;
            float av0 = sA[r0 * AST + kk + t];
            float av1 = sA[(r0 + 8) * AST + kk + t];
            float av2 = sA[r0 * AST + kk + t + 4];
            float av3 = sA[(r0 + 8) * AST + kk + t + 4];
            ahi[m][0] = f2tf(av0); alo[m][0] = f2tf(av0 - __uint_as_float(ahi[m][0]));
            ahi[m][1] = f2tf(av1); alo[m][1] = f2tf(av1 - __uint_as_float(ahi[m][1]));
            ahi[m][2] = f2tf(av2); alo[m][2] = f2tf(av2 - __uint_as_float(ahi[m][2]));
            ahi[m][3] = f2tf(av3); alo[m][3] = f2tf(av3 - __uint_as_float(ahi[m][3]));
        }
#pragma unroll
        for (int ct = 0; ct < 8; ct++) {
            int col = ncol + ct * 8 + g;
            uint2 w0 = sW2[(kk + t) * WST2 + col];
            uint2 w1 = sW2[(kk + t + 4) * WST2 + col];
#pragma unroll
            for (int m = 0; m < 2; m++) {
                MMA8(acc[m][ct], ahi[m][0], ahi[m][1], ahi[m][2], ahi[m][3], w0.x, w1.x);
                MMA8(acc[m][ct], ahi[m][0], ahi[m][1], ahi[m][2], ahi[m][3], w0.y, w1.y);
                MMA8(acc[m][ct], alo[m][0], alo[m][1], alo[m][2], alo[m][3], w0.x, w1.x);
            }
        }
    }
}

__device__ __forceinline__ void mma_epilogue(float acc[2][8][4],
                                             const float* __restrict__ bias,
                                             float* __restrict__ out,
                                             int base, int mrow, int ncol,
                                             int g, int t, int relu) {
#pragma unroll
    for (int m = 0; m < 2; m++) {
#pragma unroll
        for (int ct = 0; ct < 8; ct++) {
            int row = base + mrow + m * 16 + g;
            int col = ncol + ct * 8 + 2 * t;
            float b0 = bias[col], b1 = bias[col + 1];
            float v0 = acc[m][ct][0] + b0, v1 = acc[m][ct][1] + b1;
            float v2 = acc[m][ct][2] + b0, v3 = acc[m][ct][3] + b1;
            if (relu) {
                v0 = fmaxf(v0, 0.f); v1 = fmaxf(v1, 0.f);
                v2 = fmaxf(v2, 0.f); v3 = fmaxf(v3, 0.f);
            }
            *(float2*)(out + row * DD + col) = make_float2(v0, v1);
            *(float2*)(out + (row + 8) * DD + col) = make_float2(v2, v3);
        }
    }
}

#define MM_SMEM_BYTES (128 * AST * 4 + 64 * WST2 * 8)

// ---------------- tensor-core GEMM: out = [relu](A @ W + b) ----------------
__global__ __launch_bounds__(256, 2) void gemm_mma(
    const float* __restrict__ A, const uint2* __restrict__ Wsplit,
    const float* __restrict__ bias, float* __restrict__ out, int relu) {
    extern __shared__ float sm[];
    float* sA = sm;                              // [128][AST]
    uint2* sW2 = (uint2*)(sm + 128 * AST);       // [64][WST2]
    const int tid = threadIdx.x;
    const int base = blockIdx.x * 128;
    const int w = tid >> 5, lane = tid & 31, g = lane >> 2, t = lane & 3;
    const int mrow = (w & 3) * 32, ncol = (w >> 2) * 64;

    float acc[2][8][4];
#pragma unroll
    for (int m = 0; m < 2; m++)
#pragma unroll
        for (int c = 0; c < 8; c++)
#pragma unroll
            for (int j = 0; j < 4; j++) acc[m][c][j] = 0.f;

#pragma unroll
    for (int kc = 0; kc < 2; kc++) {
        load_sA_chunk(sA, A, base, kc * 64, tid);
        load_sW_chunk(sW2, Wsplit, kc * 64, tid);
        __syncthreads();
        mma_chunk(sA, sW2, acc, mrow, ncol, g, t);
        __syncthreads();
    }
    mma_epilogue(acc, bias, out, base, mrow, ncol, g, t, relu);
}

// ---------------- tensor-core dilated conv ----------------
__global__ __launch_bounds__(256, 2) void conv_mma(
    const float* __restrict__ X, const uint2* __restrict__ Wsplit3,
    const float* __restrict__ bias, float* __restrict__ out, int dil) {
    extern __shared__ float sm[];
    float* sA = sm;
    uint2* sW2 = (uint2*)(sm + 128 * AST);
    const int tid = threadIdx.x;
    const int base = blockIdx.x * 128;
    const int w = tid >> 5, lane = tid & 31, g = lane >> 2, t = lane & 3;
    const int mrow = (w & 3) * 32, ncol = (w >> 2) * 64;

    float acc[2][8][4];
#pragma unroll
    for (int m = 0; m < 2; m++)
#pragma unroll
        for (int c = 0; c < 8; c++)
#pragma unroll
            for (int j = 0; j < 4; j++) acc[m][c][j] = 0.f;

    for (int tp = 0; tp < 3; tp++) {
        const int shift = (tp - 1) * dil;
#pragma unroll
        for (int kc = 0; kc < 2; kc++) {
            load_sA_chunk_g(sA, X, base + shift, kc * 64, tid);
            load_sW_chunk(sW2, Wsplit3 + tp * DD * DD, kc * 64, tid);
            __syncthreads();
            mma_chunk(sA, sW2, acc, mrow, ncol, g, t);
            __syncthreads();
        }
    }
    mma_epilogue(acc, bias, out, base, mrow, ncol, g, t, 0);
}

// ---------------- BN stats / apply ----------------
__global__ void bn3_stats(const float* __restrict__ c1, const float* __restrict__ c2,
                          const float* __restrict__ c3) {
    const int ch = threadIdx.x;
    const int rows = NN / 512;
    const int r0 = blockIdx.x * rows;
    float s1 = 0, q1 = 0, s2 = 0, q2 = 0, s3 = 0, q3 = 0;
    for (int r = r0; r < r0 + rows; r++) {
        int o = r * DD + ch;
        float v1 = c1[o], v2 = c2[o], v3 = c3[o];
        float x1 = fmaxf(v1, 0.f) + v2;
        float x2 = fmaxf(v2, 0.f) + v3;
        float x3 = fmaxf(v3, 0.f) + v1;
        s1 += x1; q1 = fmaf(x1, x1, q1);
        s2 += x2; q2 = fmaf(x2, x2, q2);
        s3 += x3; q3 = fmaf(x3, x3, q3);
    }
    atomicAdd(&g_stats[0 * DD + ch], s1); atomicAdd(&g_stats[1 * DD + ch], q1);
    atomicAdd(&g_stats[2 * DD + ch], s2); atomicAdd(&g_stats[3 * DD + ch], q2);
    atomicAdd(&g_stats[4 * DD + ch], s3); atomicAdd(&g_stats[5 * DD + ch], q3);
}

__global__ void bn3_apply(float* __restrict__ c1, float* __restrict__ c2,
                          float* __restrict__ c3, const float* __restrict__ g,
                          const float* __restrict__ b) {
    int idx = blockIdx.x * blockDim.x + threadIdx.x;
    int ch = idx & (DD - 1);
    float v1 = c1[idx], v2 = c2[idx], v3 = c3[idx];
    float x1 = fmaxf(v1, 0.f) + v2;
    float x2 = fmaxf(v2, 0.f) + v3;
    float x3 = fmaxf(v3, 0.f) + v1;
    const float inv = 1.f / (float)NN;
    float mu1 = g_stats[0 * DD + ch] * inv;
    float va1 = g_stats[1 * DD + ch] * inv - mu1 * mu1;
    float mu2 = g_stats[2 * DD + ch] * inv;
    float va2 = g_stats[3 * DD + ch] * inv - mu2 * mu2;
    float mu3 = g_stats[4 * DD + ch] * inv;
    float va3 = g_stats[5 * DD + ch] * inv - mu3 * mu3;
    float gg = g[ch], bb = b[ch];
    c1[idx] = (x1 - mu1) * rsqrtf(va1 + EPSV) * gg + bb;
    c2[idx] = (x2 - mu2) * rsqrtf(va2 + EPSV) * gg + bb;
    c3[idx] = (x3 - mu3) * rsqrtf(va3 + EPSV) * gg + bb;
}

__global__ void bn1_apply(float* __restrict__ x, const float* __restrict__ g,
                          const float* __restrict__ b) {
    int idx = blockIdx.x * blockDim.x + threadIdx.x;
    int ch = idx & (DD - 1);
    const float inv = 1.f / (float)NN;
    float mu = g_stats[ch] * inv;
    float va = g_stats[DD + ch] * inv - mu * mu;
    x[idx] = (x[idx] - mu) * rsqrtf(va + EPSV) * g[ch] + b[ch];
}

// ---------------- press conv fused with bn1 stats ----------------
__global__ void press_stats(const float* __restrict__ a1, const float* __restrict__ a2,
                            const float* __restrict__ a3, const float* __restrict__ pw,
                            const float* __restrict__ pb, float* __restrict__ out) {
    const int d = threadIdx.x;
    const int rows = NN / 512;
    const int r0 = blockIdx.x * rows;
    float w00 = pw[0], w01 = pw[1], w02 = pw[2];
    float w10 = pw[3], w11 = pw[4], w12 = pw[5];
    float w20 = pw[6], w21 = pw[7], w22 = pw[8];
    float pbias = pb[0];
    float s = 0.f, q = 0.f;
    for (int r = r0; r < r0 + rows; r++) {
        const float* p1 = a1 + r * DD;
        const float* p2 = a2 + r * DD;
        const float* p3 = a3 + r * DD;
        float acc = pbias;
        if (d > 0) acc += w00 * p1[d - 1] + w10 * p2[d - 1] + w20 * p3[d - 1];
        acc += w01 * p1[d] + w11 * p2[d] + w21 * p3[d];
        if (d < 127) acc += w02 * p1[d + 1] + w12 * p2[d + 1] + w22 * p3[d + 1];
        out[r * DD + d] = acc;
        s += acc; q = fmaf(acc, acc, q);
    }
    atomicAdd(&g_stats[d], s);
    atomicAdd(&g_stats[DD + d], q);
}

// ---------------- per-graph pooling ----------------
__global__ void pool_kernel(const float* __restrict__ h2, const float* __restrict__ h3,
                            const float* __restrict__ h4, const int* __restrict__ gid) {
    const int ch = threadIdx.x;
    const int rows = NN / 512;
    const int r0 = blockIdx.x * rows;
    int cur = gid[r0];
    float s2 = 0, s3 = 0, s4 = 0;
    for (int r = r0; r < r0 + rows; r++) {
        int g = gid[r];
        if (g != cur) {
            atomicAdd(&g_hg[cur * 3 * DD + ch], s2);
            atomicAdd(&g_hg[cur * 3 * DD + DD + ch], s3);
            atomicAdd(&g_hg[cur * 3 * DD + 2 * DD + ch], s4);
            s2 = s3 = s4 = 0;
            cur = g;
        }
        int o = r * DD + ch;
        s2 += h2[o]; s3 += h3[o]; s4 += h4[o];
    }
    atomicAdd(&g_hg[cur * 3 * DD + ch], s2);
    atomicAdd(&g_hg[cur * 3 * DD + DD + ch], s3);
    atomicAdd(&g_hg[cur * 3 * DD + 2 * DD + ch], s4);
}

// ---------------- final classifier ----------------
__global__ void classify(const float* __restrict__ cl1w, const float* __restrict__ cl1b,
                         const float* __restrict__ cl2w, const float* __restrict__ cl2b,
                         float* __restrict__ out) {
    __shared__ float mid[DD];
    int t = threadIdx.x;
    for (int b = 0; b < BBG; b++) {
        float acc = cl1b[t];
        for (int k = 0; k < 3 * DD; k++) acc = fmaf(g_hg[b * 3 * DD + k], cl1w[t * 3 * DD + k], acc);
        mid[t] = acc;
        __syncthreads();
        if (t < 5) {
            float o = cl2b[t];
            for (int k = 0; k < DD; k++) o = fmaf(mid[k], cl2w[t * DD + k], o);
            out[b * 5 + t] = o;
        }
        __syncthreads();
    }
}

// ---------------- host launch ----------------
extern "C" void kernel_launch(void* const* d_in, const int* in_sizes, int n_in,
                              void* d_out, int out_size) {
    int o = (in_sizes[5] == 1) ? 6 : 5;
    const float* h   = (const float*)d_in[0];
    const float* ew  = (const float*)d_in[1];
    const int*   src = (const int*)d_in[2];
    const int*   dst = (const int*)d_in[3];
    const int*   gid = (const int*)d_in[4];
    const float* c1w = (const float*)d_in[o + 0];
    const float* c1b = (const float*)d_in[o + 1];
    const float* c2w = (const float*)d_in[o + 2];
    const float* c2b = (const float*)d_in[o + 3];
    const float* c3w = (const float*)d_in[o + 4];
    const float* c3b = (const float*)d_in[o + 5];
    const float* pw  = (const float*)d_in[o + 6];
    const float* pb  = (const float*)d_in[o + 7];
    const float* g11w = (const float*)d_in[o + 8];
    const float* g11b = (const float*)d_in[o + 9];
    const float* g12w = (const float*)d_in[o + 10];
    const float* g12b = (const float*)d_in[o + 11];
    const float* g13w = (const float*)d_in[o + 12];
    const float* g13b = (const float*)d_in[o + 13];
    const float* g2w  = (const float*)d_in[o + 14];
    const float* g2b  = (const float*)d_in[o + 15];
    const float* g3w  = (const float*)d_in[o + 16];
    const float* g3b  = (const float*)d_in[o + 17];
    const float* g4w  = (const float*)d_in[o + 18];
    const float* g4b  = (const float*)d_in[o + 19];
    const float* bng  = (const float*)d_in[o + 20];
    const float* bnb  = (const float*)d_in[o + 21];
    const float* cl1w = (const float*)d_in[o + 22];
    const float* cl1b = (const float*)d_in[o + 23];
    const float* cl2w = (const float*)d_in[o + 24];
    const float* cl2b = (const float*)d_in[o + 25];
    float* out = (float*)d_out;

    float *A, *B, *C, *a1, *a2, *a3, *agg;
    uint2* wsp;
    cudaGetSymbolAddress((void**)&A, g_A);
    cudaGetSymbolAddress((void**)&B, g_B);
    cudaGetSymbolAddress((void**)&C, g_C);
    cudaGetSymbolAddress((void**)&a1, g_a1);
    cudaGetSymbolAddress((void**)&a2, g_a2);
    cudaGetSymbolAddress((void**)&a3, g_a3);
    cudaGetSymbolAddress((void**)&agg, g_agg);
    cudaGetSymbolAddress((void**)&wsp, g_wsplit);

    cudaFuncSetAttribute(gemm_mma, cudaFuncAttributeMaxDynamicSharedMemorySize, MM_SMEM_BYTES);
    cudaFuncSetAttribute(conv_mma, cudaFuncAttributeMaxDynamicSharedMemorySize, MM_SMEM_BYTES);

    // ---- dense front-end first (so ncu's capture slot lands on conv_mma) ----
    prep_conv_w<<<(3 * DD * DD + 255) / 256, 256>>>(c1w, c2w, c3w);
    prep_wsplit<<<(15 * DD * DD + 255) / 256, 256>>>(g11w, g12w, g13w, g2w, g3w, g4w);
    conv_mma<<<NN / 128, 256, MM_SMEM_BYTES>>>(h, wsp + 0 * 3 * DD * DD, c1b, A, 1);
    conv_mma<<<NN / 128, 256, MM_SMEM_BYTES>>>(h, wsp + 1 * 3 * DD * DD, c2b, B, 2);
    conv_mma<<<NN / 128, 256, MM_SMEM_BYTES>>>(h, wsp + 2 * 3 * DD * DD, c3b, C, 3);

    zero_stats_hg<<<24, 256>>>();
    bn3_stats<<<512, DD>>>(A, B, C);
    bn3_apply<<<NN * DD / 256, 256>>>(A, B, C, bng, bnb);

    // ---- CSR build (needed before first agg_gather) ----
    zero_degcur<<<NN / 512, 512>>>();
    hist_dst<<<EE / 512, 512>>>(dst);
    scan1<<<128, 1024>>>();
    scan2<<<1, 128>>>();
    scan3<<<128, 1024>>>();
    csr_fill<<<EE / 512, 512>>>(src, dst, ew);

#define GCONV(IN, WIDX, BIAS, OUT)                                             \
    agg_gather<<<NN / 8, 256>>>(IN, agg);                                      \
    gemm_mma<<<NN / 128, 256, MM_SMEM_BYTES>>>(IN == IN ? (const float*)(IN) : 0, \
        wsp + (9 + WIDX) * DD * DD, BIAS, OUT, 1);

    // note: gemm input is agg, not IN — expand manually to avoid macro confusion
#undef GCONV
#define GCONV(IN, WIDX, BIAS, OUT)                                             \
    agg_gather<<<NN / 8, 256>>>(IN, agg);                                      \
    gemm_mma<<<NN / 128, 256, MM_SMEM_BYTES>>>(agg, wsp + (9 + WIDX) * DD * DD, BIAS, OUT, 1);

    GCONV(A, 0, g11b, a1)
    GCONV(B, 1, g12b, a2)
    GCONV(C, 2, g13b, a3)

    zero_stats_hg<<<24, 256>>>();
    press_stats<<<512, DD>>>(a1, a2, a3, pw, pb, A);
    bn1_apply<<<NN * DD / 256, 256>>>(A, bng, bnb);

    GCONV(A, 3, g2b, B)   // ac_h2
    GCONV(B, 4, g3b, C)   // ac_h3
    GCONV(C, 5, g4b, a1)  // ac_h4

    pool_kernel<<<512, DD>>>(B, C, a1, gid);
    classify<<<1, DD>>>(cl1w, cl1b, cl2w, cl2b, out);
#undef GCONV
}